// round 5
// baseline (speedup 1.0000x reference)
#include <cuda_runtime.h>

#define N_NODES 50000
#define N_EDGES 800000
#define D       96
#define H2      32
#define OUTD    4
#define CH      (D/4)        // 24 float4 chunks per row

// Scratch (no allocations allowed)
__device__ float g_z1[N_NODES * D];        // layer1 aggregated input
__device__ float g_y2[N_NODES * H2];       // h @ W2a  (pre-aggregation, pre-bias)
__device__ float g_z2[N_NODES * H2];       // layer2 aggregated (32-dim)
__device__ int   g_deg[N_NODES];
__device__ int   g_rowptr[N_NODES + 1];
__device__ int   g_cursor[N_NODES];
__device__ int   g_ebuf[N_EDGES];

// ---------------- f32x2 packed helpers ----------------
__device__ __forceinline__ unsigned long long pack2(float lo, float hi) {
    unsigned long long r;
    asm("mov.b64 %0, {%1, %2};" : "=l"(r) : "f"(lo), "f"(hi));
    return r;
}
__device__ __forceinline__ void unpack2(unsigned long long v, float& lo, float& hi) {
    asm("mov.b64 {%0, %1}, %2;" : "=f"(lo), "=f"(hi) : "l"(v));
}
__device__ __forceinline__ unsigned long long fma2(unsigned long long a,
                                                   unsigned long long b,
                                                   unsigned long long c) {
    unsigned long long d;
    asm("fma.rn.f32x2 %0, %1, %2, %3;" : "=l"(d) : "l"(a), "l"(b), "l"(c));
    return d;
}

// ---------------- CSR build ----------------

__global__ void k_hist(const int* __restrict__ ei, int* __restrict__ deg) {
    int e = blockIdx.x * blockDim.x + threadIdx.x;
    if (e < N_EDGES) atomicAdd(&deg[ei[N_EDGES + e]], 1);
}

// single-block scan: 1024 threads x 49 items
#define SCT 1024
#define IPT 49
__global__ __launch_bounds__(SCT)
void k_scan(const int* __restrict__ deg, int* __restrict__ rowptr,
            int* __restrict__ cursor) {
    __shared__ int s[SCT];
    int t = threadIdx.x;
    int base = t * IPT;
    int sum = 0;
    #pragma unroll 7
    for (int i = 0; i < IPT; i++) {
        int idx = base + i;
        if (idx < N_NODES) sum += deg[idx];
    }
    s[t] = sum;
    __syncthreads();
    for (int off = 1; off < SCT; off <<= 1) {
        int add = (t >= off) ? s[t - off] : 0;
        __syncthreads();
        s[t] += add;
        __syncthreads();
    }
    int running = s[t] - sum;   // exclusive prefix
    #pragma unroll 7
    for (int i = 0; i < IPT; i++) {
        int idx = base + i;
        if (idx < N_NODES) {
            rowptr[idx] = running;
            cursor[idx] = running;
            running += deg[idx];
        }
    }
    if (t == SCT - 1) rowptr[N_NODES] = N_EDGES;
}

__global__ void k_fill(const int* __restrict__ ei, int* __restrict__ cursor,
                       int* __restrict__ ebuf) {
    int e = blockIdx.x * blockDim.x + threadIdx.x;
    if (e < N_EDGES) {
        int dst = ei[N_EDGES + e];
        int pos = atomicAdd(&cursor[dst], 1);
        ebuf[pos] = ei[e];
    }
}

// ---------------- fused scale + gather (96-dim, warp per node) ----------------
__global__ __launch_bounds__(256)
void k_gagg(const float* __restrict__ feat, const float* __restrict__ eps,
            const int* __restrict__ rowptr, const int* __restrict__ ebuf,
            float* __restrict__ z) {
    int warp = (blockIdx.x * blockDim.x + threadIdx.x) >> 5;
    int lane = threadIdx.x & 31;
    if (warp >= N_NODES) return;
    int beg = rowptr[warp];
    int end = rowptr[warp + 1];
    const float4* f4 = reinterpret_cast<const float4*>(feat);
    float4 acc = make_float4(0.f, 0.f, 0.f, 0.f);
    if (lane < CH) {
        float s = 1.0f + *eps;
        float4 v = f4[warp * CH + lane];
        acc.x = s * v.x; acc.y = s * v.y; acc.z = s * v.z; acc.w = s * v.w;
    }
    int e = beg;
    for (; e + 4 <= end; e += 4) {
        int s0 = __ldg(&ebuf[e + 0]);
        int s1 = __ldg(&ebuf[e + 1]);
        int s2 = __ldg(&ebuf[e + 2]);
        int s3 = __ldg(&ebuf[e + 3]);
        if (lane < CH) {
            float4 v0 = f4[s0 * CH + lane];
            float4 v1 = f4[s1 * CH + lane];
            float4 v2 = f4[s2 * CH + lane];
            float4 v3 = f4[s3 * CH + lane];
            acc.x += v0.x + v1.x + v2.x + v3.x;
            acc.y += v0.y + v1.y + v2.y + v3.y;
            acc.z += v0.z + v1.z + v2.z + v3.z;
            acc.w += v0.w + v1.w + v2.w + v3.w;
        }
    }
    for (; e < end; e++) {
        int src = __ldg(&ebuf[e]);
        if (lane < CH) {
            float4 v = f4[src * CH + lane];
            acc.x += v.x; acc.y += v.y; acc.z += v.z; acc.w += v.w;
        }
    }
    if (lane < CH) reinterpret_cast<float4*>(z)[warp * CH + lane] = acc;
}

// ---------------- gather in 32-dim space (8 lanes per node) ----------------
__global__ __launch_bounds__(256)
void k_gagg32(const float* __restrict__ y2, const float* __restrict__ eps,
              const int* __restrict__ rowptr, const int* __restrict__ ebuf,
              float* __restrict__ z) {
    int t = blockIdx.x * blockDim.x + threadIdx.x;
    int node = t >> 3;
    int c = t & 7;                 // float4 chunk 0..7
    if (node >= N_NODES) return;
    int beg = rowptr[node];
    int end = rowptr[node + 1];
    const float4* f4 = reinterpret_cast<const float4*>(y2);
    float s = 1.0f + *eps;
    float4 v = f4[node * 8 + c];
    float4 acc = make_float4(s * v.x, s * v.y, s * v.z, s * v.w);
    int e = beg;
    for (; e + 4 <= end; e += 4) {
        int s0 = __ldg(&ebuf[e + 0]);
        int s1 = __ldg(&ebuf[e + 1]);
        int s2 = __ldg(&ebuf[e + 2]);
        int s3 = __ldg(&ebuf[e + 3]);
        float4 v0 = f4[s0 * 8 + c];
        float4 v1 = f4[s1 * 8 + c];
        float4 v2 = f4[s2 * 8 + c];
        float4 v3 = f4[s3 * 8 + c];
        acc.x += v0.x + v1.x + v2.x + v3.x;
        acc.y += v0.y + v1.y + v2.y + v3.y;
        acc.z += v0.z + v1.z + v2.z + v3.z;
        acc.w += v0.w + v1.w + v2.w + v3.w;
    }
    for (; e < end; e++) {
        int src = __ldg(&ebuf[e]);
        float4 w = f4[src * 8 + c];
        acc.x += w.x; acc.y += w.y; acc.z += w.z; acc.w += w.w;
    }
    reinterpret_cast<float4*>(z)[node * 8 + c] = acc;
}

// ---------------- MLP1 (+ fused y2 = h @ W2a), f32x2 packed ----------------
// 64-row tile, 192 threads. Main matmuls: thread tile 8 rows x 4 cols,
// rows packed in pairs. Activations kept K-major in smem (stride 66, even).
#define M1   64
#define ZSTR 66
__global__ __launch_bounds__(192)
void k_mlp1(const float* __restrict__ z,
            const float* __restrict__ W1a, const float* __restrict__ b1a,
            const float* __restrict__ W1b, const float* __restrict__ b1b,
            const float* __restrict__ W2a,
            float* __restrict__ y2) {
    __shared__ float zs[96 * ZSTR];    // 25344 B  (z -> t -> h, K-major)
    __shared__ float Wm[48 * 96];      // 18432 B  (total 43776 B)
    const int tid = threadIdx.x;
    const int cg = tid % 24;
    const int rg = tid / 24;           // 0..7
    const int c0 = cg * 4;
    const int r0 = rg * 8;
    const int row0 = blockIdx.x * M1;

    // stage z transposed: zs[k][row]
    for (int i = tid; i < M1 * CH; i += 192) {
        int kc = i % CH, r = i / CH;
        float4 v = (row0 + r < N_NODES)
                 ? reinterpret_cast<const float4*>(z)[(row0 + r) * CH + kc]
                 : make_float4(0.f, 0.f, 0.f, 0.f);
        zs[(kc * 4 + 0) * ZSTR + r] = v.x;
        zs[(kc * 4 + 1) * ZSTR + r] = v.y;
        zs[(kc * 4 + 2) * ZSTR + r] = v.z;
        zs[(kc * 4 + 3) * ZSTR + r] = v.w;
    }

    unsigned long long acc[4][4];      // [rowpair][col]

    // ======== matmul1: t = relu(z @ W1a + b1a) ========
    {
        float4 b = *reinterpret_cast<const float4*>(&b1a[c0]);
        unsigned long long b0 = pack2(b.x, b.x), b1p = pack2(b.y, b.y),
                           b2p = pack2(b.z, b.z), b3p = pack2(b.w, b.w);
        #pragma unroll
        for (int rp = 0; rp < 4; rp++) {
            acc[rp][0] = b0; acc[rp][1] = b1p; acc[rp][2] = b2p; acc[rp][3] = b3p;
        }
        for (int kh = 0; kh < 2; kh++) {
            __syncthreads();
            for (int i = tid; i < 48 * 96 / 4; i += 192)
                reinterpret_cast<float4*>(Wm)[i] =
                    reinterpret_cast<const float4*>(W1a + kh * 48 * 96)[i];
            __syncthreads();
            #pragma unroll 8
            for (int k = 0; k < 48; k++) {
                int kg = kh * 48 + k;
                float4 w = *reinterpret_cast<float4*>(&Wm[k * 96 + c0]);
                unsigned long long w0 = pack2(w.x, w.x), w1 = pack2(w.y, w.y),
                                   w2 = pack2(w.z, w.z), w3 = pack2(w.w, w.w);
                const unsigned long long* zp =
                    reinterpret_cast<const unsigned long long*>(&zs[kg * ZSTR + r0]);
                unsigned long long zv0 = zp[0], zv1 = zp[1], zv2 = zp[2], zv3 = zp[3];
                acc[0][0] = fma2(zv0, w0, acc[0][0]);
                acc[0][1] = fma2(zv0, w1, acc[0][1]);
                acc[0][2] = fma2(zv0, w2, acc[0][2]);
                acc[0][3] = fma2(zv0, w3, acc[0][3]);
                acc[1][0] = fma2(zv1, w0, acc[1][0]);
                acc[1][1] = fma2(zv1, w1, acc[1][1]);
                acc[1][2] = fma2(zv1, w2, acc[1][2]);
                acc[1][3] = fma2(zv1, w3, acc[1][3]);
                acc[2][0] = fma2(zv2, w0, acc[2][0]);
                acc[2][1] = fma2(zv2, w1, acc[2][1]);
                acc[2][2] = fma2(zv2, w2, acc[2][2]);
                acc[2][3] = fma2(zv2, w3, acc[2][3]);
                acc[3][0] = fma2(zv3, w0, acc[3][0]);
                acc[3][1] = fma2(zv3, w1, acc[3][1]);
                acc[3][2] = fma2(zv3, w2, acc[3][2]);
                acc[3][3] = fma2(zv3, w3, acc[3][3]);
            }
        }
        __syncthreads();   // everyone done reading zs
        #pragma unroll
        for (int rp = 0; rp < 4; rp++)
            #pragma unroll
            for (int j = 0; j < 4; j++) {
                float lo, hi; unpack2(acc[rp][j], lo, hi);
                zs[(c0 + j) * ZSTR + r0 + 2 * rp + 0] = fmaxf(lo, 0.f);
                zs[(c0 + j) * ZSTR + r0 + 2 * rp + 1] = fmaxf(hi, 0.f);
            }
    }

    // ======== matmul2: h = relu(t @ W1b + b1b) ========
    {
        float4 b = *reinterpret_cast<const float4*>(&b1b[c0]);
        unsigned long long b0 = pack2(b.x, b.x), b1p = pack2(b.y, b.y),
                           b2p = pack2(b.z, b.z), b3p = pack2(b.w, b.w);
        #pragma unroll
        for (int rp = 0; rp < 4; rp++) {
            acc[rp][0] = b0; acc[rp][1] = b1p; acc[rp][2] = b2p; acc[rp][3] = b3p;
        }
        for (int kh = 0; kh < 2; kh++) {
            __syncthreads();   // covers t-store (kh=0) / compute done (kh=1)
            for (int i = tid; i < 48 * 96 / 4; i += 192)
                reinterpret_cast<float4*>(Wm)[i] =
                    reinterpret_cast<const float4*>(W1b + kh * 48 * 96)[i];
            __syncthreads();
            #pragma unroll 8
            for (int k = 0; k < 48; k++) {
                int kg = kh * 48 + k;
                float4 w = *reinterpret_cast<float4*>(&Wm[k * 96 + c0]);
                unsigned long long w0 = pack2(w.x, w.x), w1 = pack2(w.y, w.y),
                                   w2 = pack2(w.z, w.z), w3 = pack2(w.w, w.w);
                const unsigned long long* zp =
                    reinterpret_cast<const unsigned long long*>(&zs[kg * ZSTR + r0]);
                unsigned long long zv0 = zp[0], zv1 = zp[1], zv2 = zp[2], zv3 = zp[3];
                acc[0][0] = fma2(zv0, w0, acc[0][0]);
                acc[0][1] = fma2(zv0, w1, acc[0][1]);
                acc[0][2] = fma2(zv0, w2, acc[0][2]);
                acc[0][3] = fma2(zv0, w3, acc[0][3]);
                acc[1][0] = fma2(zv1, w0, acc[1][0]);
                acc[1][1] = fma2(zv1, w1, acc[1][1]);
                acc[1][2] = fma2(zv1, w2, acc[1][2]);
                acc[1][3] = fma2(zv1, w3, acc[1][3]);
                acc[2][0] = fma2(zv2, w0, acc[2][0]);
                acc[2][1] = fma2(zv2, w1, acc[2][1]);
                acc[2][2] = fma2(zv2, w2, acc[2][2]);
                acc[2][3] = fma2(zv2, w3, acc[2][3]);
                acc[3][0] = fma2(zv3, w0, acc[3][0]);
                acc[3][1] = fma2(zv3, w1, acc[3][1]);
                acc[3][2] = fma2(zv3, w2, acc[3][2]);
                acc[3][3] = fma2(zv3, w3, acc[3][3]);
            }
        }
        __syncthreads();
        #pragma unroll
        for (int rp = 0; rp < 4; rp++)
            #pragma unroll
            for (int j = 0; j < 4; j++) {
                float lo, hi; unpack2(acc[rp][j], lo, hi);
                zs[(c0 + j) * ZSTR + r0 + 2 * rp + 0] = fmaxf(lo, 0.f);
                zs[(c0 + j) * ZSTR + r0 + 2 * rp + 1] = fmaxf(hi, 0.f);
            }
        __syncthreads();
    }

    // ======== y2 = h @ W2a  (no bias, pre-aggregation) ========
    for (int i = tid; i < D * H2 / 4; i += 192)
        reinterpret_cast<float4*>(Wm)[i] = reinterpret_cast<const float4*>(W2a)[i];
    __syncthreads();
    if (tid < 128) {
        const int cg2 = tid % 8, rg2 = tid / 8;   // 8 col groups x 16 row groups
        const int cb = cg2 * 4, rb = rg2 * 4;
        unsigned long long a2[2][4];
        unsigned long long zz = pack2(0.f, 0.f);
        #pragma unroll
        for (int rp = 0; rp < 2; rp++)
            #pragma unroll
            for (int j = 0; j < 4; j++) a2[rp][j] = zz;
        #pragma unroll 8
        for (int k = 0; k < D; k++) {
            float4 w = *reinterpret_cast<float4*>(&Wm[k * H2 + cb]);
            unsigned long long w0 = pack2(w.x, w.x), w1 = pack2(w.y, w.y),
                               w2 = pack2(w.z, w.z), w3 = pack2(w.w, w.w);
            const unsigned long long* hp =
                reinterpret_cast<const unsigned long long*>(&zs[k * ZSTR + rb]);
            unsigned long long h0 = hp[0], h1 = hp[1];
            a2[0][0] = fma2(h0, w0, a2[0][0]);
            a2[0][1] = fma2(h0, w1, a2[0][1]);
            a2[0][2] = fma2(h0, w2, a2[0][2]);
            a2[0][3] = fma2(h0, w3, a2[0][3]);
            a2[1][0] = fma2(h1, w0, a2[1][0]);
            a2[1][1] = fma2(h1, w1, a2[1][1]);
            a2[1][2] = fma2(h1, w2, a2[1][2]);
            a2[1][3] = fma2(h1, w3, a2[1][3]);
        }
        #pragma unroll
        for (int rp = 0; rp < 2; rp++) {
            float lo0, hi0, lo1, hi1, lo2, hi2, lo3, hi3;
            unpack2(a2[rp][0], lo0, hi0);
            unpack2(a2[rp][1], lo1, hi1);
            unpack2(a2[rp][2], lo2, hi2);
            unpack2(a2[rp][3], lo3, hi3);
            int rlo = row0 + rb + 2 * rp;
            if (rlo < N_NODES)
                *reinterpret_cast<float4*>(&y2[(long long)rlo * H2 + cb]) =
                    make_float4(lo0, lo1, lo2, lo3);
            if (rlo + 1 < N_NODES)
                *reinterpret_cast<float4*>(&y2[(long long)(rlo + 1) * H2 + cb]) =
                    make_float4(hi0, hi1, hi2, hi3);
        }
    }
}

// ---------------- MLP2 tail: a=relu(z2+b2a); b=relu(a@W2b+b2b); out=b@Wh+bh
__global__ __launch_bounds__(256)
void k_mlp2(const float* __restrict__ z2,
            const float* __restrict__ b2a, const float* __restrict__ W2b,
            const float* __restrict__ b2b, const float* __restrict__ Wh,
            const float* __restrict__ bh, float* __restrict__ out) {
    __shared__ float W2b_s[H2 * H2];
    __shared__ float Wh_s[H2 * OUTD];
    __shared__ float b2a_s[H2];
    __shared__ float b2b_s[H2];
    const int tid = threadIdx.x;
    for (int i = tid; i < H2 * H2 / 4; i += 256)
        reinterpret_cast<float4*>(W2b_s)[i] = reinterpret_cast<const float4*>(W2b)[i];
    if (tid < H2 * OUTD) Wh_s[tid] = Wh[tid];
    if (tid < H2) { b2a_s[tid] = b2a[tid]; b2b_s[tid] = b2b[tid]; }
    __syncthreads();

    int row = blockIdx.x * 256 + tid;
    if (row >= N_NODES) return;

    float a[H2];
    const float4* zr = reinterpret_cast<const float4*>(z2 + (long long)row * H2);
    #pragma unroll
    for (int c = 0; c < 8; c++) {
        float4 v = zr[c];
        a[c * 4 + 0] = fmaxf(v.x + b2a_s[c * 4 + 0], 0.f);
        a[c * 4 + 1] = fmaxf(v.y + b2a_s[c * 4 + 1], 0.f);
        a[c * 4 + 2] = fmaxf(v.z + b2a_s[c * 4 + 2], 0.f);
        a[c * 4 + 3] = fmaxf(v.w + b2a_s[c * 4 + 3], 0.f);
    }
    float o0 = bh[0], o1 = bh[1], o2 = bh[2], o3 = bh[3];
    #pragma unroll 4
    for (int j = 0; j < H2; j++) {
        float bj = b2b_s[j];
        #pragma unroll
        for (int k = 0; k < H2; k++) bj = fmaf(a[k], W2b_s[k * H2 + j], bj);
        bj = fmaxf(bj, 0.f);
        o0 = fmaf(bj, Wh_s[j * OUTD + 0], o0);
        o1 = fmaf(bj, Wh_s[j * OUTD + 1], o1);
        o2 = fmaf(bj, Wh_s[j * OUTD + 2], o2);
        o3 = fmaf(bj, Wh_s[j * OUTD + 3], o3);
    }
    *reinterpret_cast<float4*>(&out[(long long)row * OUTD]) =
        make_float4(o0, o1, o2, o3);
}

extern "C" void kernel_launch(void* const* d_in, const int* in_sizes, int n_in,
                              void* d_out, int out_size) {
    const float* x    = (const float*)d_in[0];
    const int*   ei   = (const int*)  d_in[1];
    const float* eps1 = (const float*)d_in[2];
    const float* eps2 = (const float*)d_in[3];
    const float* W1a  = (const float*)d_in[4];
    const float* b1a  = (const float*)d_in[5];
    const float* W1b  = (const float*)d_in[6];
    const float* b1b  = (const float*)d_in[7];
    const float* W2a  = (const float*)d_in[8];
    const float* b2a  = (const float*)d_in[9];
    const float* W2b  = (const float*)d_in[10];
    const float* b2b  = (const float*)d_in[11];
    const float* Wh   = (const float*)d_in[12];
    const float* bh   = (const float*)d_in[13];
    float* out = (float*)d_out;

    float *z1, *y2, *z2;
    int *deg, *rowptr, *cursor, *ebuf;
    cudaGetSymbolAddress((void**)&z1, g_z1);
    cudaGetSymbolAddress((void**)&y2, g_y2);
    cudaGetSymbolAddress((void**)&z2, g_z2);
    cudaGetSymbolAddress((void**)&deg, g_deg);
    cudaGetSymbolAddress((void**)&rowptr, g_rowptr);
    cudaGetSymbolAddress((void**)&cursor, g_cursor);
    cudaGetSymbolAddress((void**)&ebuf, g_ebuf);

    const int eb = (N_EDGES + 255) / 256;
    const int gagg_blocks   = (N_NODES * 32 + 255) / 256;
    const int gagg32_blocks = (N_NODES * 8 + 255) / 256;
    const int mlp1_blocks   = (N_NODES + M1 - 1) / M1;
    const int mlp2_blocks   = (N_NODES + 255) / 256;

    // CSR build (4 launches)
    cudaMemsetAsync(deg, 0, N_NODES * sizeof(int));
    k_hist<<<eb, 256>>>(ei, deg);
    k_scan<<<1, SCT>>>(deg, rowptr, cursor);
    k_fill<<<eb, 256>>>(ei, cursor, ebuf);

    // Layer 1 + first matmul of layer 2 (fused)
    k_gagg<<<gagg_blocks, 256>>>(x, eps1, rowptr, ebuf, z1);
    k_mlp1<<<mlp1_blocks, 192>>>(z1, W1a, b1a, W1b, b1b, W2a, y2);

    // Layer 2 aggregation in 32-dim space + tail
    k_gagg32<<<gagg32_blocks, 256>>>(y2, eps2, rowptr, ebuf, z2);
    k_mlp2<<<mlp2_blocks, 256>>>(z2, b2a, W2b, b2b, Wh, bh, out);
}